// round 11
// baseline (speedup 1.0000x reference)
#include <cuda_runtime.h>
#include <cuda_bf16.h>

#define BATCH     1000000
#define FEAT      128
#define NCLASS    1000
#define NTHREADS  256
#define NBLOCKS   1184                      // 148 SMs * 8 blocks -> one full wave at 32 regs
#define WARPS_PER_BLOCK (NTHREADS / 32)
#define NWARPS    (NBLOCKS * WARPS_PER_BLOCK)   // 9472
#define TILE_ROWS 4
#define NTILES    (BATCH / TILE_ROWS)       // 250000
#define FULL_ROUNDS (NTILES / NWARPS)       // 26 fully-balanced static rounds
#define TAIL_START  (FULL_ROUNDS * NWARPS)  // 246272; 3728 tail tiles go dynamic

// Per-block partial sums (every block writes its slot every launch -> no zeroing).
__device__ float g_partials[NBLOCKS];
// Ticket counter for last-block-done reduction; reset by the last block each launch.
__device__ int g_count = 0;
// Dynamic tail ticket; starts at TAIL_START, reset by the last block each launch.
__device__ unsigned g_tile = TAIL_START;

__device__ __forceinline__ float warp_sum(float s) {
    #pragma unroll
    for (int o = 16; o; o >>= 1) s += __shfl_xor_sync(0xffffffffu, s, o);
    return s;
}

// Process one 4-row tile; returns the 16x-replicated hinge contribution.
__device__ __forceinline__ float do_tile(
    const float4* __restrict__ x4, const float4* __restrict__ c4,
    const int* __restrict__ labels, unsigned t, int lane, float margin)
{
    const unsigned tbase = t * (unsigned)TILE_ROWS;
    const int mylab = __ldcs(&labels[tbase + (lane & 3)]);  // one 16B sector
    float acc = 0.0f;

    #pragma unroll
    for (int k = 0; k < TILE_ROWS / 2; k++) {
        const int lab0 = __shfl_sync(0xffffffffu, mylab, 2 * k);
        const int lab1 = __shfl_sync(0xffffffffu, mylab, 2 * k + 1);

        float4 xv0 = __ldcs(&x4[(tbase + 2u * k) * 32u + lane]);
        float4 xv1 = __ldcs(&x4[(tbase + 2u * k + 1u) * 32u + lane]);
        float4 cv0 = __ldg(&c4[(unsigned)lab0 * 32u + lane]);
        float4 cv1 = __ldg(&c4[(unsigned)lab1 * 32u + lane]);

        float a0 = xv0.x - cv0.x, a1 = xv0.y - cv0.y, a2 = xv0.z - cv0.z, a3 = xv0.w - cv0.w;
        float b0 = xv1.x - cv1.x, b1 = xv1.y - cv1.y, b2 = xv1.z - cv1.z, b3 = xv1.w - cv1.w;
        float s0 = a0*a0 + a1*a1 + a2*a2 + a3*a3;   // row 2k partial
        float s1 = b0*b0 + b1*b1 + b2*b2 + b3*b3;   // row 2k+1 partial

        // Paired reduction: one cross-half exchange (row0 -> lanes 0-15,
        // row1 -> lanes 16-31) then 4 butterflies within halves.
        // 5 shuffles for 2 rows; result replicated x16 per half.
        const bool hi = (lane & 16) != 0;
        float send = hi ? s0 : s1;
        float recv = __shfl_xor_sync(0xffffffffu, send, 16);
        float z = (hi ? s1 : s0) + recv;
        #pragma unroll
        for (int o = 8; o; o >>= 1) z += __shfl_xor_sync(0xffffffffu, z, o);
        acc += fmaxf(z - margin, 0.0f);
    }
    return acc;
}

__global__ __launch_bounds__(NTHREADS, 8) void hinge_fused_kernel(
    const float* __restrict__ x,
    const int* __restrict__ labels,
    const float* __restrict__ centers,
    float* __restrict__ out)
{
    const int lane = threadIdx.x & 31;
    const int wid  = threadIdx.x >> 5;
    const int gw   = blockIdx.x * WARPS_PER_BLOCK + wid;

    const float4* __restrict__ x4 = reinterpret_cast<const float4*>(x);
    const float4* __restrict__ c4 = reinterpret_cast<const float4*>(centers);

    // margin = ||centers[0] - centers[1]|| / 10 (tiny, L1-hit)
    float4 ca = __ldg(&c4[lane]);
    float4 cb = __ldg(&c4[32 + lane]);
    float md0 = ca.x - cb.x, md1 = ca.y - cb.y, md2 = ca.z - cb.z, md3 = ca.w - cb.w;
    const float margin = sqrtf(warp_sum(md0*md0 + md1*md1 + md2*md2 + md3*md3)) * 0.1f;

    float acc = 0.0f;   // 16x-replicated hinge sums; rescaled by 1/16 at the end

    // Phase 1: 26 static rounds -- every warp does exactly FULL_ROUNDS tiles,
    // perfectly balanced, identical steady state to the proven R8 loop.
    #pragma unroll 1
    for (unsigned t = gw; t < TAIL_START; t += NWARPS)
        acc += do_tile(x4, c4, labels, t, lane, margin);

    // Phase 2: dynamic tail -- the 3728 remaining tiles go to whichever warps
    // finish phase 1 first (~99.9% overall utilization). At most ~2 atomics
    // per warp, all at the very end, so no steady-state pollution.
    for (;;) {
        unsigned tk;
        if (lane == 0) tk = atomicAdd(&g_tile, 1u);
        tk = __shfl_sync(0xffffffffu, tk, 0);
        if (tk >= NTILES) break;
        acc += do_tile(x4, c4, labels, tk, lane, margin);
    }

    // warp_sum(acc) = 16 * (true warp hinge sum); exact 1/16 rescale.
    const float wacc = warp_sum(acc) * 0.0625f;

    // Block reduce.
    __shared__ float smem[WARPS_PER_BLOCK];
    __shared__ bool is_last;
    if (lane == 0) smem[wid] = wacc;
    __syncthreads();
    if (threadIdx.x == 0) {
        float s = 0.0f;
        #pragma unroll
        for (int i = 0; i < WARPS_PER_BLOCK; i++) s += smem[i];
        g_partials[blockIdx.x] = s;
        __threadfence();
        int ticket = atomicAdd(&g_count, 1);
        is_last = (ticket == NBLOCKS - 1);
    }
    __syncthreads();

    // Last block reduces all partials (f64, fixed order), writes the scalar,
    // and resets the schedulers for the next launch / graph replay.
    if (is_last) {
        __shared__ double sm[NTHREADS];
        double s = 0.0;
        for (int i = threadIdx.x; i < NBLOCKS; i += NTHREADS)
            s += (double)g_partials[i];
        sm[threadIdx.x] = s;
        __syncthreads();
        #pragma unroll
        for (int o = NTHREADS / 2; o; o >>= 1) {
            if (threadIdx.x < o) sm[threadIdx.x] += sm[threadIdx.x + o];
            __syncthreads();
        }
        if (threadIdx.x == 0) {
            out[0] = (float)(sm[0] / (4.0 * (double)BATCH));
            g_count = 0;
            g_tile  = TAIL_START;
        }
    }
}

extern "C" void kernel_launch(void* const* d_in, const int* in_sizes, int n_in,
                              void* d_out, int out_size)
{
    const float* x       = (const float*)d_in[0];   // [1e6, 128] f32
    const int*   labels  = (const int*)  d_in[1];   // [1e6] i32
    const float* centers = (const float*)d_in[2];   // [1000, 128] f32
    float*       out     = (float*)d_out;           // scalar f32

    hinge_fused_kernel<<<NBLOCKS, NTHREADS>>>(x, labels, centers, out);
}

// round 12
// speedup vs baseline: 1.0027x; 1.0027x over previous
#include <cuda_runtime.h>
#include <cuda_bf16.h>

#define BATCH     1000000
#define FEAT      128
#define NCLASS    1000
#define NTHREADS  256
#define NBLOCKS   3552                      // 148 SMs * 8 resident * 3 waves: backfill absorbs CTA spread
#define WARPS_PER_BLOCK (NTHREADS / 32)
#define NWARPS    (NBLOCKS * WARPS_PER_BLOCK)   // 28416
#define TILE_ROWS 4
#define NTILES    (BATCH / TILE_ROWS)       // 250000 tiles; 8-9 tiles per warp

// Per-block partial sums (every block writes its slot every launch -> no zeroing).
__device__ float g_partials[NBLOCKS];
// Ticket counter for last-block-done reduction; reset by the last block each launch.
__device__ int g_count = 0;

__device__ __forceinline__ float warp_sum(float s) {
    #pragma unroll
    for (int o = 16; o; o >>= 1) s += __shfl_xor_sync(0xffffffffu, s, o);
    return s;
}

__global__ __launch_bounds__(NTHREADS, 8) void hinge_fused_kernel(
    const float* __restrict__ x,
    const int* __restrict__ labels,
    const float* __restrict__ centers,
    float* __restrict__ out)
{
    const int lane = threadIdx.x & 31;
    const int wid  = threadIdx.x >> 5;
    const int gw   = blockIdx.x * WARPS_PER_BLOCK + wid;

    const float4* __restrict__ x4 = reinterpret_cast<const float4*>(x);
    const float4* __restrict__ c4 = reinterpret_cast<const float4*>(centers);

    // margin = ||centers[0] - centers[1]|| / 10 (tiny, L1-hit)
    float4 ca = __ldg(&c4[lane]);
    float4 cb = __ldg(&c4[32 + lane]);
    float md0 = ca.x - cb.x, md1 = ca.y - cb.y, md2 = ca.z - cb.z, md3 = ca.w - cb.w;
    const float margin = sqrtf(warp_sum(md0*md0 + md1*md1 + md2*md2 + md3*md3)) * 0.1f;

    float acc = 0.0f;   // 16x-replicated hinge sums; rescaled by 1/16 at the end

    // R8 mainloop verbatim: stride-distributed 4-row tiles, one coalesced
    // label sector per tile, labels distributed via shuffles. No unroll
    // pragma on this loop -- ptxas overlaps iterations on its own.
    for (unsigned t = gw; t < NTILES; t += NWARPS) {
        const unsigned tbase = t * (unsigned)TILE_ROWS;
        const int mylab = __ldcs(&labels[tbase + (lane & 3)]);

        #pragma unroll
        for (int k = 0; k < TILE_ROWS / 2; k++) {
            const int lab0 = __shfl_sync(0xffffffffu, mylab, 2 * k);
            const int lab1 = __shfl_sync(0xffffffffu, mylab, 2 * k + 1);

            float4 xv0 = __ldcs(&x4[(tbase + 2u * k) * 32u + lane]);
            float4 xv1 = __ldcs(&x4[(tbase + 2u * k + 1u) * 32u + lane]);
            float4 cv0 = __ldg(&c4[(unsigned)lab0 * 32u + lane]);
            float4 cv1 = __ldg(&c4[(unsigned)lab1 * 32u + lane]);

            float a0 = xv0.x - cv0.x, a1 = xv0.y - cv0.y, a2 = xv0.z - cv0.z, a3 = xv0.w - cv0.w;
            float b0 = xv1.x - cv1.x, b1 = xv1.y - cv1.y, b2 = xv1.z - cv1.z, b3 = xv1.w - cv1.w;
            float s0 = a0*a0 + a1*a1 + a2*a2 + a3*a3;   // row 2k partial
            float s1 = b0*b0 + b1*b1 + b2*b2 + b3*b3;   // row 2k+1 partial

            // Paired reduction: one cross-half exchange (row0 -> lanes 0-15,
            // row1 -> lanes 16-31), then 4 butterflies within halves.
            // 5 shuffles for 2 rows; result replicated x16 per half.
            const bool hi = (lane & 16) != 0;
            float send = hi ? s0 : s1;
            float recv = __shfl_xor_sync(0xffffffffu, send, 16);
            float z = (hi ? s1 : s0) + recv;
            #pragma unroll
            for (int o = 8; o; o >>= 1) z += __shfl_xor_sync(0xffffffffu, z, o);
            acc += fmaxf(z - margin, 0.0f);
        }
    }

    // warp_sum(acc) = 16 * (true warp hinge sum); exact 1/16 rescale.
    const float wacc = warp_sum(acc) * 0.0625f;

    // Block reduce.
    __shared__ float smem[WARPS_PER_BLOCK];
    __shared__ bool is_last;
    if (lane == 0) smem[wid] = wacc;
    __syncthreads();
    if (threadIdx.x == 0) {
        float s = 0.0f;
        #pragma unroll
        for (int i = 0; i < WARPS_PER_BLOCK; i++) s += smem[i];
        g_partials[blockIdx.x] = s;
        __threadfence();
        int ticket = atomicAdd(&g_count, 1);
        is_last = (ticket == NBLOCKS - 1);
    }
    __syncthreads();

    // Last block reduces all partials (f64, fixed order) and writes the scalar.
    if (is_last) {
        __shared__ double sm[NTHREADS];
        double s = 0.0;
        for (int i = threadIdx.x; i < NBLOCKS; i += NTHREADS)
            s += (double)g_partials[i];
        sm[threadIdx.x] = s;
        __syncthreads();
        #pragma unroll
        for (int o = NTHREADS / 2; o; o >>= 1) {
            if (threadIdx.x < o) sm[threadIdx.x] += sm[threadIdx.x + o];
            __syncthreads();
        }
        if (threadIdx.x == 0) {
            out[0] = (float)(sm[0] / (4.0 * (double)BATCH));
            g_count = 0;   // reset for next launch / graph replay
        }
    }
}

extern "C" void kernel_launch(void* const* d_in, const int* in_sizes, int n_in,
                              void* d_out, int out_size)
{
    const float* x       = (const float*)d_in[0];   // [1e6, 128] f32
    const int*   labels  = (const int*)  d_in[1];   // [1e6] i32
    const float* centers = (const float*)d_in[2];   // [1000, 128] f32
    float*       out     = (float*)d_out;           // scalar f32

    hinge_fused_kernel<<<NBLOCKS, NTHREADS>>>(x, labels, centers, out);
}

// round 14
// speedup vs baseline: 1.0332x; 1.0304x over previous
#include <cuda_runtime.h>
#include <cuda_bf16.h>

#define BATCH     1000000
#define FEAT      128
#define NCLASS    1000
#define NTHREADS  256
#define NBLOCKS   1184                      // 148 SMs * 8 blocks -> one full wave (proven best)
#define WARPS_PER_BLOCK (NTHREADS / 32)
#define NWARPS    (NBLOCKS * WARPS_PER_BLOCK)   // 9472
#define TILE_ROWS 4
#define NTILES    (BATCH / TILE_ROWS)       // 250000 tiles, 27 rounds, 97.8% utilization

// Per-block partial sums (every block writes its slot every launch -> no zeroing).
__device__ float g_partials[NBLOCKS];
// Ticket counter for last-block-done reduction; reset by the last block each launch.
__device__ int g_count = 0;

__device__ __forceinline__ float warp_sum(float s) {
    #pragma unroll
    for (int o = 16; o; o >>= 1) s += __shfl_xor_sync(0xffffffffu, s, o);
    return s;
}

__global__ __launch_bounds__(NTHREADS, 8) void hinge_fused_kernel(
    const float* __restrict__ x,
    const int* __restrict__ labels,
    const float* __restrict__ centers,
    float* __restrict__ out)
{
    const int lane = threadIdx.x & 31;
    const int wid  = threadIdx.x >> 5;
    const int gw   = blockIdx.x * WARPS_PER_BLOCK + wid;

    const float4* __restrict__ x4 = reinterpret_cast<const float4*>(x);
    const float4* __restrict__ c4 = reinterpret_cast<const float4*>(centers);

    // margin = ||centers[0] - centers[1]|| / 10 (tiny, L1-hit)
    float4 ca = __ldg(&c4[lane]);
    float4 cb = __ldg(&c4[32 + lane]);
    float md0 = ca.x - cb.x, md1 = ca.y - cb.y, md2 = ca.z - cb.z, md3 = ca.w - cb.w;
    const float margin = sqrtf(warp_sum(md0*md0 + md1*md1 + md2*md2 + md3*md3)) * 0.1f;

    // Group-per-row: 8-lane quarter-warp g owns row tbase+g of each tile.
    const int g  = lane >> 3;   // 0..3 -> row within tile
    const int gl = lane & 7;    // lane within group

    float acc = 0.0f;   // 8x-replicated hinge sums; rescaled by 1/8 at the end

    // Static stride-distributed 4-row tiles (proven R8 schedule). Per tile:
    //   1 broadcast label LDG (one 16B sector/warp, no label shuffles),
    //   8 front-batched 128-bit loads (each instruction = 4 fully-consumed
    //   128B lines: 4 rows x one 128B chunk),
    //   3 shuffles total (group-local butterflies) vs 14 in the warp-per-row
    //   form -> ~80% less MIO shuffle pressure competing with the LDG stream.
    for (unsigned t = gw; t < NTILES; t += NWARPS) {
        const unsigned tbase = t * (unsigned)TILE_ROWS;
        const int lab = __ldcs(&labels[tbase + g]);

        const float4* __restrict__ xrow = x4 + (tbase + (unsigned)g) * 32u;
        const float4* __restrict__ crow = c4 + (unsigned)lab * 32u;

        float s = 0.0f;   // this lane's 16-feature partial of ||x_row - c_row||^2
        #pragma unroll
        for (int i = 0; i < 4; i++) {
            float4 xv = __ldcs(&xrow[gl + 8 * i]);
            float4 cv = __ldg (&crow[gl + 8 * i]);
            float d0 = xv.x - cv.x, d1 = xv.y - cv.y;
            float d2 = xv.z - cv.z, d3 = xv.w - cv.w;
            s += d0*d0 + d1*d1 + d2*d2 + d3*d3;
        }

        // 3 butterflies within the 8-lane group finish the row (xor of bits
        // 0..2 stays inside the group). Row sum replicated x8.
        #pragma unroll
        for (int o = 4; o; o >>= 1) s += __shfl_xor_sync(0xffffffffu, s, o);

        acc += fmaxf(s - margin, 0.0f);
    }

    // warp_sum(acc) = 8 * (true warp hinge sum); exact 1/8 rescale.
    const float wacc = warp_sum(acc) * 0.125f;

    // Block reduce.
    __shared__ float smem[WARPS_PER_BLOCK];
    __shared__ bool is_last;
    if (lane == 0) smem[wid] = wacc;
    __syncthreads();
    if (threadIdx.x == 0) {
        float s = 0.0f;
        #pragma unroll
        for (int i = 0; i < WARPS_PER_BLOCK; i++) s += smem[i];
        g_partials[blockIdx.x] = s;
        __threadfence();
        int ticket = atomicAdd(&g_count, 1);
        is_last = (ticket == NBLOCKS - 1);
    }
    __syncthreads();

    // Last block reduces all partials (f64, fixed order) and writes the scalar.
    if (is_last) {
        __shared__ double sm[NTHREADS];
        double s = 0.0;
        for (int i = threadIdx.x; i < NBLOCKS; i += NTHREADS)
            s += (double)g_partials[i];
        sm[threadIdx.x] = s;
        __syncthreads();
        #pragma unroll
        for (int o = NTHREADS / 2; o; o >>= 1) {
            if (threadIdx.x < o) sm[threadIdx.x] += sm[threadIdx.x + o];
            __syncthreads();
        }
        if (threadIdx.x == 0) {
            out[0] = (float)(sm[0] / (4.0 * (double)BATCH));
            g_count = 0;   // reset for next launch / graph replay
        }
    }
}

extern "C" void kernel_launch(void* const* d_in, const int* in_sizes, int n_in,
                              void* d_out, int out_size)
{
    const float* x       = (const float*)d_in[0];   // [1e6, 128] f32
    const int*   labels  = (const int*)  d_in[1];   // [1e6] i32
    const float* centers = (const float*)d_in[2];   // [1000, 128] f32
    float*       out     = (float*)d_out;           // scalar f32

    hinge_fused_kernel<<<NBLOCKS, NTHREADS>>>(x, labels, centers, out);
}